// round 1
// baseline (speedup 1.0000x reference)
#include <cuda_runtime.h>
#include <cuda_bf16.h>
#include <cstdint>

#define N_NODES 50000
#define N_EDGES 1600000
#define FEAT    128
#define NUM_RELS 8

// Scratch: transformed features hw[r][n][o], fp32. 204.8 MB device global (allowed).
__device__ float g_hw[(size_t)NUM_RELS * N_NODES * FEAT];

// ---------------------------------------------------------------------------
// GEMM: hw[r] = x @ W[r].  Tile 64 rows x 128 cols, whole K=128 in smem.
// 128 threads, each computes 8x8 outputs.
// ---------------------------------------------------------------------------
__global__ __launch_bounds__(128) void rgcn_gemm_kernel(
    const float* __restrict__ x, const float* __restrict__ w)
{
    __shared__ float ws[FEAT][FEAT];        // 64 KB  W[r][k][o]
    __shared__ float xs[64][FEAT + 1];      // 33 KB  x tile (padded: stride 129)

    const int r    = blockIdx.y;
    const int row0 = blockIdx.x * 64;
    const int tid  = threadIdx.x;

    // Load W[r] (16384 floats) via float4, 32 per thread.
    const float4* w4 = (const float4*)(w + (size_t)r * FEAT * FEAT);
    #pragma unroll
    for (int i = tid; i < FEAT * FEAT / 4; i += 128) {
        float4 v = w4[i];
        int k = i >> 5;            // row in W (128 floats = 32 float4 per row)
        int c = (i & 31) << 2;     // col
        ws[k][c] = v.x; ws[k][c + 1] = v.y; ws[k][c + 2] = v.z; ws[k][c + 3] = v.w;
    }
    // Load x tile (64 x 128 floats) via float4.
    #pragma unroll
    for (int i = tid; i < 64 * FEAT / 4; i += 128) {
        int rr = i >> 5;
        int c  = (i & 31) << 2;
        int grow = row0 + rr;
        float4 v = make_float4(0.f, 0.f, 0.f, 0.f);
        if (grow < N_NODES) v = ((const float4*)x)[(size_t)grow * 32 + (i & 31)];
        xs[rr][c] = v.x; xs[rr][c + 1] = v.y; xs[rr][c + 2] = v.z; xs[rr][c + 3] = v.w;
    }
    __syncthreads();

    const int tx = tid & 15;   // 16 col groups of 8 cols
    const int ty = tid >> 4;   // 8 row groups of 8 rows

    float acc[8][8];
    #pragma unroll
    for (int i = 0; i < 8; i++)
        #pragma unroll
        for (int j = 0; j < 8; j++) acc[i][j] = 0.f;

    #pragma unroll 4
    for (int k = 0; k < FEAT; k++) {
        float xv[8], wv[8];
        #pragma unroll
        for (int i = 0; i < 8; i++) xv[i] = xs[ty * 8 + i][k];
        #pragma unroll
        for (int j = 0; j < 8; j++) wv[j] = ws[k][tx * 8 + j];
        #pragma unroll
        for (int i = 0; i < 8; i++)
            #pragma unroll
            for (int j = 0; j < 8; j++)
                acc[i][j] = fmaf(xv[i], wv[j], acc[i][j]);
    }

    float* out = g_hw + (size_t)r * N_NODES * FEAT;
    #pragma unroll
    for (int i = 0; i < 8; i++) {
        int grow = row0 + ty * 8 + i;
        if (grow < N_NODES) {
            float4* o4 = (float4*)(out + (size_t)grow * FEAT + tx * 8);
            o4[0] = make_float4(acc[i][0], acc[i][1], acc[i][2], acc[i][3]);
            o4[1] = make_float4(acc[i][4], acc[i][5], acc[i][6], acc[i][7]);
        }
    }
}

// ---------------------------------------------------------------------------
// Scatter: one warp per edge. Gather hw[rel,src] (float4/lane), scale by norm,
// vectorized reduction into out[dst] (red.global.add.v4.f32 -> L2 atomics).
// ---------------------------------------------------------------------------
__global__ __launch_bounds__(256) void rgcn_scatter_kernel(
    const float* __restrict__ norm,
    const int*   __restrict__ src,
    const int*   __restrict__ dst,
    const int*   __restrict__ rel,
    float*       __restrict__ out)
{
    const int warp = (blockIdx.x * blockDim.x + threadIdx.x) >> 5;
    const int lane = threadIdx.x & 31;
    if (warp >= N_EDGES) return;

    const int   s  = src[warp];
    const int   d  = dst[warp];
    const int   rt = rel[warp];
    const float nm = norm[warp];

    const float4* hp = (const float4*)(g_hw + ((size_t)rt * N_NODES + s) * FEAT);
    float4 v = hp[lane];
    v.x *= nm; v.y *= nm; v.z *= nm; v.w *= nm;

    float* o = out + (size_t)d * FEAT + lane * 4;
    asm volatile("red.global.add.v4.f32 [%0], {%1,%2,%3,%4};"
                 :: "l"(o), "f"(v.x), "f"(v.y), "f"(v.z), "f"(v.w)
                 : "memory");
}

// ---------------------------------------------------------------------------
// Epilogue: out = relu(out + bias)
// ---------------------------------------------------------------------------
__global__ __launch_bounds__(256) void rgcn_bias_relu_kernel(
    float* __restrict__ out, const float* __restrict__ bias)
{
    const int i = blockIdx.x * blockDim.x + threadIdx.x;   // over N*FEAT/4
    if (i >= N_NODES * FEAT / 4) return;
    const int c = (i & 31) << 2;
    float4 v = ((float4*)out)[i];
    float4 b = ((const float4*)bias)[c >> 2];
    v.x = fmaxf(v.x + b.x, 0.f);
    v.y = fmaxf(v.y + b.y, 0.f);
    v.z = fmaxf(v.z + b.z, 0.f);
    v.w = fmaxf(v.w + b.w, 0.f);
    ((float4*)out)[i] = v;
}

// ---------------------------------------------------------------------------
// Launch. Inputs (metadata order): x, norm, weight, bias, src, dst, rel_type.
// ---------------------------------------------------------------------------
extern "C" void kernel_launch(void* const* d_in, const int* in_sizes, int n_in,
                              void* d_out, int out_size)
{
    const float* x      = (const float*)d_in[0];
    const float* norm   = (const float*)d_in[1];
    const float* weight = (const float*)d_in[2];
    const float* bias   = (const float*)d_in[3];
    const int*   src    = (const int*)d_in[4];
    const int*   dst    = (const int*)d_in[5];
    const int*   rel    = (const int*)d_in[6];
    float*       out    = (float*)d_out;

    // Zero accumulation target.
    cudaMemsetAsync(out, 0, (size_t)N_NODES * FEAT * sizeof(float), 0);

    // 1) hw[r] = x @ W[r]
    dim3 ggrid((N_NODES + 63) / 64, NUM_RELS);
    rgcn_gemm_kernel<<<ggrid, 128>>>(x, weight);

    // 2) scatter messages
    const int warps = N_EDGES;
    const int threads = 256;
    const int blocks = (warps * 32 + threads - 1) / threads;
    rgcn_scatter_kernel<<<blocks, threads>>>(norm, src, dst, rel, out);

    // 3) bias + relu
    const int n4 = N_NODES * FEAT / 4;
    rgcn_bias_relu_kernel<<<(n4 + 255) / 256, 256>>>(out, bias);
}

// round 3
// speedup vs baseline: 1.6683x; 1.6683x over previous
#include <cuda_runtime.h>
#include <cuda_fp16.h>
#include <cstdint>

#define N_NODES 50000
#define N_EDGES 1600000
#define FEAT    128
#define NUM_RELS 8
#define TILE_M  128
#define N_TILES 391              /* ceil(50000/128) */

// ---------------------------------------------------------------------------
// Device scratch
// ---------------------------------------------------------------------------
__device__ __half g_hw_h[(size_t)NUM_RELS * N_NODES * FEAT];   // 102.4 MB fp16
__device__ float  g_xr[(size_t)N_NODES * FEAT];                // 25.6 MB tf32-rounded x
__device__ float  g_wr[(size_t)NUM_RELS * FEAT * FEAT];        // 512 KB tf32-rounded, col-permuted W

// ---------------------------------------------------------------------------
// Helpers
// ---------------------------------------------------------------------------
__device__ __forceinline__ uint32_t smem_to_u32(const void* p) {
    uint32_t a;
    asm("{ .reg .u64 t; cvta.to.shared.u64 t, %1; cvt.u32.u64 %0, t; }" : "=r"(a) : "l"(p));
    return a;
}
__device__ __forceinline__ float to_tf32(float f) {
    uint32_t r; asm("cvt.rna.tf32.f32 %0, %1;" : "=r"(r) : "f"(f));
    return __uint_as_float(r);
}
__device__ __forceinline__ void cp_async16(uint32_t dst, const void* src, int srcsize) {
    asm volatile("cp.async.cg.shared.global [%0], [%1], 16, %2;"
                 :: "r"(dst), "l"(src), "r"(srcsize) : "memory");
}
#define CP_COMMIT() asm volatile("cp.async.commit_group;" ::: "memory")

__device__ __forceinline__ void mma_tf32(float c[4],
                                         uint32_t a0, uint32_t a1, uint32_t a2, uint32_t a3,
                                         uint32_t b0, uint32_t b1) {
    asm volatile("mma.sync.aligned.m16n8k8.row.col.f32.tf32.tf32.f32 "
                 "{%0,%1,%2,%3}, {%4,%5,%6,%7}, {%8,%9}, {%0,%1,%2,%3};"
                 : "+f"(c[0]), "+f"(c[1]), "+f"(c[2]), "+f"(c[3])
                 : "r"(a0), "r"(a1), "r"(a2), "r"(a3), "r"(b0), "r"(b1));
}

// ---------------------------------------------------------------------------
// Prep: x -> tf32-rounded copy
// ---------------------------------------------------------------------------
__global__ __launch_bounds__(256) void prep_x_kernel(const float* __restrict__ x)
{
    int i = blockIdx.x * blockDim.x + threadIdx.x;        // over float4
    if (i >= N_NODES * FEAT / 4) return;
    float4 v = ((const float4*)x)[i];
    v.x = to_tf32(v.x); v.y = to_tf32(v.y); v.z = to_tf32(v.z); v.w = to_tf32(v.w);
    ((float4*)g_xr)[i] = v;
}

// Prep: W[r][k][o] -> tf32-rounded, column-permuted so the mma C-fragment of
// each thread covers 16 contiguous global output columns.
// smem/gemm col position s maps to global col:
//   g(s) = (s/64)*64 + ((s%8)/2)*16 + ((s%64)/8)*2 + (s&1)
__global__ __launch_bounds__(256) void prep_w_kernel(const float* __restrict__ w)
{
    int i = blockIdx.x * blockDim.x + threadIdx.x;        // over elements of g_wr
    if (i >= NUM_RELS * FEAT * FEAT) return;
    int rk = i >> 7;                                      // r*128 + k
    int s  = i & 127;
    int g  = (s >> 6) * 64 + ((s & 7) >> 1) * 16 + ((s & 63) >> 3) * 2 + (s & 1);
    g_wr[i] = to_tf32(w[(size_t)rk * FEAT + g]);
}

// ---------------------------------------------------------------------------
// GEMM via mma.sync tf32: per CTA one 128-row tile x all 8 relations.
// smem: x tile [128][132] f32 + W double-buffer 2x[128][136] f32  (~202 KB)
// ---------------------------------------------------------------------------
#define XS_STRIDE 132
#define WS_STRIDE 136
#define XS_FLOATS (128 * XS_STRIDE)
#define WS_FLOATS (128 * WS_STRIDE)
#define GEMM_SMEM ((XS_FLOATS + 2 * WS_FLOATS) * 4)

__global__ __launch_bounds__(256) void rgcn_gemm_mma()
{
    extern __shared__ float sm[];
    float* xs = sm;
    float* ws = sm + XS_FLOATS;
    const uint32_t xs_u = smem_to_u32(xs);
    const uint32_t ws_u = smem_to_u32(ws);

    const int tid  = threadIdx.x;
    const int tile = blockIdx.x;
    const int row0 = tile * TILE_M;

    // async load x tile (zero-fill OOB rows)
    for (int i = tid; i < 4096; i += 256) {
        int row = i >> 5, c = i & 31;
        int sz = (row0 + row < N_NODES) ? 16 : 0;
        cp_async16(xs_u + (uint32_t)(row * XS_STRIDE + c * 4) * 4,
                   g_xr + (size_t)(row0 + row) * FEAT + c * 4, sz);
    }
    // async load W[0] into buf0
    for (int i = tid; i < 4096; i += 256) {
        int k = i >> 5, c = i & 31;
        cp_async16(ws_u + (uint32_t)(k * WS_STRIDE + c * 4) * 4,
                   g_wr + (size_t)k * FEAT + c * 4, 16);
    }
    CP_COMMIT();
    // async load W[1] into buf1
    for (int i = tid; i < 4096; i += 256) {
        int k = i >> 5, c = i & 31;
        cp_async16(ws_u + (uint32_t)(WS_FLOATS + k * WS_STRIDE + c * 4) * 4,
                   g_wr + (size_t)FEAT * FEAT + (size_t)k * FEAT + c * 4, 16);
    }
    CP_COMMIT();
    asm volatile("cp.async.wait_group 1;" ::: "memory");
    __syncthreads();

    const int wid = tid >> 5, lane = tid & 31;
    const int wm = wid >> 1, wn = wid & 1;
    const int r0 = wm * 32;           // warp row base within tile
    const int n0 = wn * 64;           // warp col base (smem position space)
    const int tr = lane >> 2, tc = lane & 3;

    for (int rel = 0; rel < NUM_RELS; rel++) {
        const float* wb = ws + (rel & 1) * WS_FLOATS;

        float c[2][8][4];
        #pragma unroll
        for (int mi = 0; mi < 2; mi++)
            #pragma unroll
            for (int ni = 0; ni < 8; ni++)
                #pragma unroll
                for (int j = 0; j < 4; j++) c[mi][ni][j] = 0.f;

        #pragma unroll
        for (int kk = 0; kk < 16; kk++) {
            const int k0 = kk * 8;
            uint32_t a[2][4], b[8][2];
            #pragma unroll
            for (int mi = 0; mi < 2; mi++) {
                const int rr = r0 + mi * 16 + tr;
                a[mi][0] = __float_as_uint(xs[rr * XS_STRIDE + k0 + tc]);
                a[mi][1] = __float_as_uint(xs[(rr + 8) * XS_STRIDE + k0 + tc]);
                a[mi][2] = __float_as_uint(xs[rr * XS_STRIDE + k0 + tc + 4]);
                a[mi][3] = __float_as_uint(xs[(rr + 8) * XS_STRIDE + k0 + tc + 4]);
            }
            #pragma unroll
            for (int ni = 0; ni < 8; ni++) {
                const int nn = n0 + ni * 8 + tr;
                b[ni][0] = __float_as_uint(wb[(k0 + tc) * WS_STRIDE + nn]);
                b[ni][1] = __float_as_uint(wb[(k0 + tc + 4) * WS_STRIDE + nn]);
            }
            #pragma unroll
            for (int mi = 0; mi < 2; mi++)
                #pragma unroll
                for (int ni = 0; ni < 8; ni++)
                    mma_tf32(c[mi][ni], a[mi][0], a[mi][1], a[mi][2], a[mi][3],
                             b[ni][0], b[ni][1]);
        }

        __syncthreads();                       // all warps done reading wb

        if (rel + 2 < NUM_RELS) {              // prefetch W[rel+2] into freed buffer
            for (int i = tid; i < 4096; i += 256) {
                int k = i >> 5, cc = i & 31;
                cp_async16(ws_u + (uint32_t)((rel & 1) * WS_FLOATS + k * WS_STRIDE + cc * 4) * 4,
                           g_wr + (size_t)(rel + 2) * FEAT * FEAT + (size_t)k * FEAT + cc * 4, 16);
            }
            CP_COMMIT();
        }

        // Epilogue: store C as fp16. Thread owns global cols [n0 + tc*16, +16).
        #pragma unroll
        for (int mi = 0; mi < 2; mi++) {
            #pragma unroll
            for (int p = 0; p < 2; p++) {
                const int row = row0 + r0 + mi * 16 + tr + p * 8;
                if (row < N_NODES) {
                    uint32_t h[8];
                    #pragma unroll
                    for (int ni = 0; ni < 8; ni++) {
                        __half2 hh = __floats2half2_rn(c[mi][ni][2 * p], c[mi][ni][2 * p + 1]);
                        h[ni] = *(uint32_t*)&hh;
                    }
                    uint4* dst = (uint4*)(g_hw_h + ((size_t)rel * N_NODES + row) * FEAT + n0 + tc * 16);
                    dst[0] = make_uint4(h[0], h[1], h[2], h[3]);
                    dst[1] = make_uint4(h[4], h[5], h[6], h[7]);
                }
            }
        }

        if (rel + 1 < NUM_RELS) {
            if (rel + 2 < NUM_RELS) { asm volatile("cp.async.wait_group 1;" ::: "memory"); }
            else                    { asm volatile("cp.async.wait_group 0;" ::: "memory"); }
            __syncthreads();
        }
    }
}

// ---------------------------------------------------------------------------
// Scatter: one warp per edge; gather fp16 hw[rel,src], scale, red.add.v4.f32
// ---------------------------------------------------------------------------
__global__ __launch_bounds__(256) void rgcn_scatter_kernel(
    const float* __restrict__ norm,
    const int*   __restrict__ src,
    const int*   __restrict__ dst,
    const int*   __restrict__ rel,
    float*       __restrict__ out)
{
    const int warp = (blockIdx.x * blockDim.x + threadIdx.x) >> 5;
    const int lane = threadIdx.x & 31;
    if (warp >= N_EDGES) return;

    const int   s  = src[warp];
    const int   d  = dst[warp];
    const int   rt = rel[warp];
    const float nm = norm[warp];

    const uint2* hp = (const uint2*)(g_hw_h + ((size_t)rt * N_NODES + s) * FEAT);
    uint2 hv = hp[lane];
    __half2 h0 = *(__half2*)&hv.x;
    __half2 h1 = *(__half2*)&hv.y;
    float2 f0 = __half22float2(h0);
    float2 f1 = __half22float2(h1);

    float* o = out + (size_t)d * FEAT + lane * 4;
    asm volatile("red.global.add.v4.f32 [%0], {%1,%2,%3,%4};"
                 :: "l"(o), "f"(f0.x * nm), "f"(f0.y * nm), "f"(f1.x * nm), "f"(f1.y * nm)
                 : "memory");
}

// ---------------------------------------------------------------------------
// Epilogue: out = relu(out + bias)
// ---------------------------------------------------------------------------
__global__ __launch_bounds__(256) void rgcn_bias_relu_kernel(
    float* __restrict__ out, const float* __restrict__ bias)
{
    const int i = blockIdx.x * blockDim.x + threadIdx.x;
    if (i >= N_NODES * FEAT / 4) return;
    float4 v = ((float4*)out)[i];
    float4 b = ((const float4*)bias)[i & 31];
    v.x = fmaxf(v.x + b.x, 0.f);
    v.y = fmaxf(v.y + b.y, 0.f);
    v.z = fmaxf(v.z + b.z, 0.f);
    v.w = fmaxf(v.w + b.w, 0.f);
    ((float4*)out)[i] = v;
}

// ---------------------------------------------------------------------------
extern "C" void kernel_launch(void* const* d_in, const int* in_sizes, int n_in,
                              void* d_out, int out_size)
{
    const float* x      = (const float*)d_in[0];
    const float* norm   = (const float*)d_in[1];
    const float* weight = (const float*)d_in[2];
    const float* bias   = (const float*)d_in[3];
    const int*   src    = (const int*)d_in[4];
    const int*   dst    = (const int*)d_in[5];
    const int*   rel    = (const int*)d_in[6];
    float*       out    = (float*)d_out;

    cudaFuncSetAttribute(rgcn_gemm_mma, cudaFuncAttributeMaxDynamicSharedMemorySize, GEMM_SMEM);

    cudaMemsetAsync(out, 0, (size_t)N_NODES * FEAT * sizeof(float), 0);

    prep_x_kernel<<<(N_NODES * FEAT / 4 + 255) / 256, 256>>>(x);
    prep_w_kernel<<<(NUM_RELS * FEAT * FEAT + 255) / 256, 256>>>(weight);

    rgcn_gemm_mma<<<N_TILES, 256, GEMM_SMEM>>>();

    const int blocks = (N_EDGES * 32 + 255) / 256;
    rgcn_scatter_kernel<<<blocks, 256>>>(norm, src, dst, rel, out);

    const int n4 = N_NODES * FEAT / 4;
    rgcn_bias_relu_kernel<<<(n4 + 255) / 256, 256>>>(out, bias);
}

// round 4
// speedup vs baseline: 2.0512x; 1.2295x over previous
#include <cuda_runtime.h>
#include <cuda_fp16.h>
#include <cstdint>

#define N_NODES 50000
#define N_EDGES 1600000
#define FEAT    128
#define NUM_RELS 8
#define TILE_M  128
#define N_TILES 391              /* ceil(50000/128) */
#define SCAN_B  256
#define N_SBLK  ((N_NODES + SCAN_B - 1) / SCAN_B)   /* 196 */

// ---------------------------------------------------------------------------
// Device scratch
// ---------------------------------------------------------------------------
__device__ __half g_hw_h[(size_t)NUM_RELS * N_NODES * FEAT];   // 102.4 MB fp16
__device__ float  g_xr[(size_t)N_NODES * FEAT];                // 25.6 MB tf32-rounded x
__device__ float  g_wr[(size_t)NUM_RELS * FEAT * FEAT];        // 512 KB tf32-rounded, col-permuted W
__device__ int    g_deg[N_NODES];
__device__ int    g_cur[N_NODES];
__device__ int    g_rowstart[N_NODES + 1];
__device__ int    g_bsum[N_SBLK];
__device__ int    g_eid[N_EDGES];

// ---------------------------------------------------------------------------
// Helpers
// ---------------------------------------------------------------------------
__device__ __forceinline__ uint32_t smem_to_u32(const void* p) {
    uint32_t a;
    asm("{ .reg .u64 t; cvta.to.shared.u64 t, %1; cvt.u32.u64 %0, t; }" : "=r"(a) : "l"(p));
    return a;
}
__device__ __forceinline__ float to_tf32(float f) {
    uint32_t r; asm("cvt.rna.tf32.f32 %0, %1;" : "=r"(r) : "f"(f));
    return __uint_as_float(r);
}
__device__ __forceinline__ void cp_async16(uint32_t dst, const void* src, int srcsize) {
    asm volatile("cp.async.cg.shared.global [%0], [%1], 16, %2;"
                 :: "r"(dst), "l"(src), "r"(srcsize) : "memory");
}
#define CP_COMMIT() asm volatile("cp.async.commit_group;" ::: "memory")

__device__ __forceinline__ void mma_tf32(float c[4],
                                         uint32_t a0, uint32_t a1, uint32_t a2, uint32_t a3,
                                         uint32_t b0, uint32_t b1) {
    asm volatile("mma.sync.aligned.m16n8k8.row.col.f32.tf32.tf32.f32 "
                 "{%0,%1,%2,%3}, {%4,%5,%6,%7}, {%8,%9}, {%0,%1,%2,%3};"
                 : "+f"(c[0]), "+f"(c[1]), "+f"(c[2]), "+f"(c[3])
                 : "r"(a0), "r"(a1), "r"(a2), "r"(a3), "r"(b0), "r"(b1));
}

// ---------------------------------------------------------------------------
// Prep: x -> tf32-rounded copy
// ---------------------------------------------------------------------------
__global__ __launch_bounds__(256) void prep_x_kernel(const float* __restrict__ x)
{
    int i = blockIdx.x * blockDim.x + threadIdx.x;        // over float4
    if (i >= N_NODES * FEAT / 4) return;
    float4 v = ((const float4*)x)[i];
    v.x = to_tf32(v.x); v.y = to_tf32(v.y); v.z = to_tf32(v.z); v.w = to_tf32(v.w);
    ((float4*)g_xr)[i] = v;
}

// Prep: W[r][k][o] -> tf32-rounded, column-permuted so the mma C-fragment of
// each thread covers 16 contiguous global output columns.
__global__ __launch_bounds__(256) void prep_w_kernel(const float* __restrict__ w)
{
    int i = blockIdx.x * blockDim.x + threadIdx.x;        // over elements of g_wr
    if (i >= NUM_RELS * FEAT * FEAT) return;
    int rk = i >> 7;                                      // r*128 + k
    int s  = i & 127;
    int g  = (s >> 6) * 64 + ((s & 7) >> 1) * 16 + ((s & 63) >> 3) * 2 + (s & 1);
    g_wr[i] = to_tf32(w[(size_t)rk * FEAT + g]);
}

// ---------------------------------------------------------------------------
// GEMM via mma.sync tf32 (unchanged from R3)
// ---------------------------------------------------------------------------
#define XS_STRIDE 132
#define WS_STRIDE 136
#define XS_FLOATS (128 * XS_STRIDE)
#define WS_FLOATS (128 * WS_STRIDE)
#define GEMM_SMEM ((XS_FLOATS + 2 * WS_FLOATS) * 4)

__global__ __launch_bounds__(256) void rgcn_gemm_mma()
{
    extern __shared__ float sm[];
    float* xs = sm;
    float* ws = sm + XS_FLOATS;
    const uint32_t xs_u = smem_to_u32(xs);
    const uint32_t ws_u = smem_to_u32(ws);

    const int tid  = threadIdx.x;
    const int tile = blockIdx.x;
    const int row0 = tile * TILE_M;

    for (int i = tid; i < 4096; i += 256) {
        int row = i >> 5, c = i & 31;
        int sz = (row0 + row < N_NODES) ? 16 : 0;
        cp_async16(xs_u + (uint32_t)(row * XS_STRIDE + c * 4) * 4,
                   g_xr + (size_t)(row0 + row) * FEAT + c * 4, sz);
    }
    for (int i = tid; i < 4096; i += 256) {
        int k = i >> 5, c = i & 31;
        cp_async16(ws_u + (uint32_t)(k * WS_STRIDE + c * 4) * 4,
                   g_wr + (size_t)k * FEAT + c * 4, 16);
    }
    CP_COMMIT();
    for (int i = tid; i < 4096; i += 256) {
        int k = i >> 5, c = i & 31;
        cp_async16(ws_u + (uint32_t)(WS_FLOATS + k * WS_STRIDE + c * 4) * 4,
                   g_wr + (size_t)FEAT * FEAT + (size_t)k * FEAT + c * 4, 16);
    }
    CP_COMMIT();
    asm volatile("cp.async.wait_group 1;" ::: "memory");
    __syncthreads();

    const int wid = tid >> 5, lane = tid & 31;
    const int wm = wid >> 1, wn = wid & 1;
    const int r0 = wm * 32;
    const int n0 = wn * 64;
    const int tr = lane >> 2, tc = lane & 3;

    for (int rel = 0; rel < NUM_RELS; rel++) {
        const float* wb = ws + (rel & 1) * WS_FLOATS;

        float c[2][8][4];
        #pragma unroll
        for (int mi = 0; mi < 2; mi++)
            #pragma unroll
            for (int ni = 0; ni < 8; ni++)
                #pragma unroll
                for (int j = 0; j < 4; j++) c[mi][ni][j] = 0.f;

        #pragma unroll
        for (int kk = 0; kk < 16; kk++) {
            const int k0 = kk * 8;
            uint32_t a[2][4], b[8][2];
            #pragma unroll
            for (int mi = 0; mi < 2; mi++) {
                const int rr = r0 + mi * 16 + tr;
                a[mi][0] = __float_as_uint(xs[rr * XS_STRIDE + k0 + tc]);
                a[mi][1] = __float_as_uint(xs[(rr + 8) * XS_STRIDE + k0 + tc]);
                a[mi][2] = __float_as_uint(xs[rr * XS_STRIDE + k0 + tc + 4]);
                a[mi][3] = __float_as_uint(xs[(rr + 8) * XS_STRIDE + k0 + tc + 4]);
            }
            #pragma unroll
            for (int ni = 0; ni < 8; ni++) {
                const int nn = n0 + ni * 8 + tr;
                b[ni][0] = __float_as_uint(wb[(k0 + tc) * WS_STRIDE + nn]);
                b[ni][1] = __float_as_uint(wb[(k0 + tc + 4) * WS_STRIDE + nn]);
            }
            #pragma unroll
            for (int mi = 0; mi < 2; mi++)
                #pragma unroll
                for (int ni = 0; ni < 8; ni++)
                    mma_tf32(c[mi][ni], a[mi][0], a[mi][1], a[mi][2], a[mi][3],
                             b[ni][0], b[ni][1]);
        }

        __syncthreads();

        if (rel + 2 < NUM_RELS) {
            for (int i = tid; i < 4096; i += 256) {
                int k = i >> 5, cc = i & 31;
                cp_async16(ws_u + (uint32_t)((rel & 1) * WS_FLOATS + k * WS_STRIDE + cc * 4) * 4,
                           g_wr + (size_t)(rel + 2) * FEAT * FEAT + (size_t)k * FEAT + cc * 4, 16);
            }
            CP_COMMIT();
        }

        #pragma unroll
        for (int mi = 0; mi < 2; mi++) {
            #pragma unroll
            for (int p = 0; p < 2; p++) {
                const int row = row0 + r0 + mi * 16 + tr + p * 8;
                if (row < N_NODES) {
                    uint32_t h[8];
                    #pragma unroll
                    for (int ni = 0; ni < 8; ni++) {
                        __half2 hh = __floats2half2_rn(c[mi][ni][2 * p], c[mi][ni][2 * p + 1]);
                        h[ni] = *(uint32_t*)&hh;
                    }
                    uint4* dst = (uint4*)(g_hw_h + ((size_t)rel * N_NODES + row) * FEAT + n0 + tc * 16);
                    dst[0] = make_uint4(h[0], h[1], h[2], h[3]);
                    dst[1] = make_uint4(h[4], h[5], h[6], h[7]);
                }
            }
        }

        if (rel + 1 < NUM_RELS) {
            if (rel + 2 < NUM_RELS) { asm volatile("cp.async.wait_group 1;" ::: "memory"); }
            else                    { asm volatile("cp.async.wait_group 0;" ::: "memory"); }
            __syncthreads();
        }
    }
}

// ---------------------------------------------------------------------------
// CSR build: zero -> hist -> scan(block) -> scan(sums) -> add offsets -> permute
// ---------------------------------------------------------------------------
__global__ __launch_bounds__(256) void csr_zero_kernel()
{
    int i = blockIdx.x * blockDim.x + threadIdx.x;
    if (i < N_NODES) { g_deg[i] = 0; g_cur[i] = 0; }
}

__global__ __launch_bounds__(256) void csr_hist_kernel(const int* __restrict__ dst)
{
    int e = blockIdx.x * blockDim.x + threadIdx.x;
    if (e < N_EDGES) atomicAdd(&g_deg[dst[e]], 1);
}

__global__ __launch_bounds__(SCAN_B) void csr_scan_block_kernel()
{
    __shared__ int sh[SCAN_B];
    int i = blockIdx.x * SCAN_B + threadIdx.x;
    int v = (i < N_NODES) ? g_deg[i] : 0;
    sh[threadIdx.x] = v;
    __syncthreads();
    #pragma unroll
    for (int o = 1; o < SCAN_B; o <<= 1) {
        int t = (threadIdx.x >= o) ? sh[threadIdx.x - o] : 0;
        __syncthreads();
        sh[threadIdx.x] += t;
        __syncthreads();
    }
    if (i < N_NODES) g_rowstart[i] = sh[threadIdx.x] - v;     // exclusive within block
    if (threadIdx.x == SCAN_B - 1) g_bsum[blockIdx.x] = sh[SCAN_B - 1];
}

__global__ __launch_bounds__(SCAN_B) void csr_scan_sums_kernel()
{
    __shared__ int sh[SCAN_B];
    int v = (threadIdx.x < N_SBLK) ? g_bsum[threadIdx.x] : 0;
    sh[threadIdx.x] = v;
    __syncthreads();
    #pragma unroll
    for (int o = 1; o < SCAN_B; o <<= 1) {
        int t = (threadIdx.x >= o) ? sh[threadIdx.x - o] : 0;
        __syncthreads();
        sh[threadIdx.x] += t;
        __syncthreads();
    }
    if (threadIdx.x < N_SBLK) g_bsum[threadIdx.x] = sh[threadIdx.x] - v;  // exclusive
}

__global__ __launch_bounds__(256) void csr_add_offsets_kernel()
{
    int i = blockIdx.x * blockDim.x + threadIdx.x;
    if (i < N_NODES) g_rowstart[i] += g_bsum[i >> 8];
    if (i == 0) g_rowstart[N_NODES] = N_EDGES;
}

__global__ __launch_bounds__(256) void csr_permute_kernel(const int* __restrict__ dst)
{
    int e = blockIdx.x * blockDim.x + threadIdx.x;
    if (e >= N_EDGES) return;
    int d = dst[e];
    int pos = atomicAdd(&g_cur[d], 1);
    g_eid[g_rowstart[d] + pos] = e;
}

// ---------------------------------------------------------------------------
// Aggregate: warp per node; chunk-load 32 edges' metadata into lanes, shfl
// broadcast, pipeline the hw-row gather one edge ahead. Fused bias+relu store.
// ---------------------------------------------------------------------------
__global__ __launch_bounds__(256) void rgcn_aggregate_kernel(
    const float* __restrict__ norm,
    const int*   __restrict__ src,
    const int*   __restrict__ rel,
    const float* __restrict__ bias,
    float*       __restrict__ out)
{
    const int warp = (blockIdx.x * blockDim.x + threadIdx.x) >> 5;
    const int lane = threadIdx.x & 31;
    if (warp >= N_NODES) return;

    const int beg = g_rowstart[warp];
    const int end = g_rowstart[warp + 1];

    float4 acc = make_float4(0.f, 0.f, 0.f, 0.f);

    for (int base = beg; base < end; base += 32) {
        int m = end - base; if (m > 32) m = 32;
        int e = 0;
        if (lane < m) e = g_eid[base + lane];
        const int   s_l = src[e];
        const int   r_l = rel[e];
        const float n_l = norm[e];

        // prefetch gather for edge 0 of chunk
        int   sn = __shfl_sync(0xffffffffu, s_l, 0);
        int   rn = __shfl_sync(0xffffffffu, r_l, 0);
        uint2 hv = ((const uint2*)(g_hw_h + ((size_t)rn * N_NODES + sn) * FEAT))[lane];

        for (int i = 0; i < m; i++) {
            const float nm  = __shfl_sync(0xffffffffu, n_l, i);
            const uint2 cur = hv;
            if (i + 1 < m) {
                sn = __shfl_sync(0xffffffffu, s_l, i + 1);
                rn = __shfl_sync(0xffffffffu, r_l, i + 1);
                hv = ((const uint2*)(g_hw_h + ((size_t)rn * N_NODES + sn) * FEAT))[lane];
            }
            float2 f0 = __half22float2(*(const __half2*)&cur.x);
            float2 f1 = __half22float2(*(const __half2*)&cur.y);
            acc.x = fmaf(f0.x, nm, acc.x);
            acc.y = fmaf(f0.y, nm, acc.y);
            acc.z = fmaf(f1.x, nm, acc.z);
            acc.w = fmaf(f1.y, nm, acc.w);
        }
    }

    const float4 b = ((const float4*)bias)[lane];
    acc.x = fmaxf(acc.x + b.x, 0.f);
    acc.y = fmaxf(acc.y + b.y, 0.f);
    acc.z = fmaxf(acc.z + b.z, 0.f);
    acc.w = fmaxf(acc.w + b.w, 0.f);
    ((float4*)(out + (size_t)warp * FEAT))[lane] = acc;
}

// ---------------------------------------------------------------------------
extern "C" void kernel_launch(void* const* d_in, const int* in_sizes, int n_in,
                              void* d_out, int out_size)
{
    const float* x      = (const float*)d_in[0];
    const float* norm   = (const float*)d_in[1];
    const float* weight = (const float*)d_in[2];
    const float* bias   = (const float*)d_in[3];
    const int*   src    = (const int*)d_in[4];
    const int*   dst    = (const int*)d_in[5];
    const int*   rel    = (const int*)d_in[6];
    float*       out    = (float*)d_out;

    cudaFuncSetAttribute(rgcn_gemm_mma, cudaFuncAttributeMaxDynamicSharedMemorySize, GEMM_SMEM);

    // --- CSR build (runs concurrently-ish with prep/gemm in stream order) ---
    csr_zero_kernel<<<(N_NODES + 255) / 256, 256>>>();
    csr_hist_kernel<<<(N_EDGES + 255) / 256, 256>>>(dst);
    csr_scan_block_kernel<<<N_SBLK, SCAN_B>>>();
    csr_scan_sums_kernel<<<1, SCAN_B>>>();
    csr_add_offsets_kernel<<<(N_NODES + 255) / 256, 256>>>();
    csr_permute_kernel<<<(N_EDGES + 255) / 256, 256>>>(dst);

    // --- transform ---
    prep_x_kernel<<<(N_NODES * FEAT / 4 + 255) / 256, 256>>>(x);
    prep_w_kernel<<<(NUM_RELS * FEAT * FEAT + 255) / 256, 256>>>(weight);
    rgcn_gemm_mma<<<N_TILES, 256, GEMM_SMEM>>>();

    // --- aggregate (CSR, no atomics) + fused bias/relu ---
    const int ablocks = (N_NODES * 32 + 255) / 256;
    rgcn_aggregate_kernel<<<ablocks, 256>>>(norm, src, rel, bias, out);
}

// round 5
// speedup vs baseline: 2.2225x; 1.0835x over previous
#include <cuda_runtime.h>
#include <cuda_fp16.h>
#include <cstdint>

#define N_NODES 50000
#define N_EDGES 1600000
#define FEAT    128
#define NUM_RELS 8
#define TILE_M  128
#define N_TILES 391              /* ceil(50000/128) */
#define SCAN_B  256
#define N_SBLK  ((N_NODES + SCAN_B - 1) / SCAN_B)   /* 196 */

// ---------------------------------------------------------------------------
// Device scratch
// ---------------------------------------------------------------------------
__device__ __half    g_hw_h[(size_t)NUM_RELS * N_NODES * FEAT]; // 102.4 MB fp16
__device__ float     g_wr[(size_t)NUM_RELS * FEAT * FEAT];      // 512 KB tf32, col-permuted W
__device__ int       g_deg[N_NODES];
__device__ int       g_cur[N_NODES];
__device__ int       g_rowstart[N_NODES + 1];
__device__ int       g_bsum[N_SBLK];
__device__ uint32_t  g_eoff[N_EDGES];                           // CSR-ordered hw-row byte offset
__device__ float     g_enorm[N_EDGES];                          // CSR-ordered norm

// ---------------------------------------------------------------------------
// Helpers
// ---------------------------------------------------------------------------
__device__ __forceinline__ uint32_t smem_to_u32(const void* p) {
    uint32_t a;
    asm("{ .reg .u64 t; cvta.to.shared.u64 t, %1; cvt.u32.u64 %0, t; }" : "=r"(a) : "l"(p));
    return a;
}
__device__ __forceinline__ float to_tf32(float f) {
    uint32_t r; asm("cvt.rna.tf32.f32 %0, %1;" : "=r"(r) : "f"(f));
    return __uint_as_float(r);
}
__device__ __forceinline__ void cp_async16(uint32_t dst, const void* src, int srcsize) {
    asm volatile("cp.async.cg.shared.global [%0], [%1], 16, %2;"
                 :: "r"(dst), "l"(src), "r"(srcsize) : "memory");
}
#define CP_COMMIT() asm volatile("cp.async.commit_group;" ::: "memory")

__device__ __forceinline__ void mma_tf32(float c[4],
                                         uint32_t a0, uint32_t a1, uint32_t a2, uint32_t a3,
                                         uint32_t b0, uint32_t b1) {
    asm volatile("mma.sync.aligned.m16n8k8.row.col.f32.tf32.tf32.f32 "
                 "{%0,%1,%2,%3}, {%4,%5,%6,%7}, {%8,%9}, {%0,%1,%2,%3};"
                 : "+f"(c[0]), "+f"(c[1]), "+f"(c[2]), "+f"(c[3])
                 : "r"(a0), "r"(a1), "r"(a2), "r"(a3), "r"(b0), "r"(b1));
}

// ---------------------------------------------------------------------------
// Prep: W[r][k][o] -> tf32-rounded, column-permuted so each thread's mma C
// fragment covers 16 contiguous global output columns.
// ---------------------------------------------------------------------------
__global__ __launch_bounds__(256) void prep_w_kernel(const float* __restrict__ w)
{
    int i = blockIdx.x * blockDim.x + threadIdx.x;
    if (i >= NUM_RELS * FEAT * FEAT) return;
    int rk = i >> 7;                                      // r*128 + k
    int s  = i & 127;
    int g  = (s >> 6) * 64 + ((s & 7) >> 1) * 16 + ((s & 63) >> 3) * 2 + (s & 1);
    g_wr[i] = to_tf32(w[(size_t)rk * FEAT + g]);
}

// ---------------------------------------------------------------------------
// GEMM via mma.sync tf32. x loaded directly (cvt.rna in smem-store path).
// ---------------------------------------------------------------------------
#define XS_STRIDE 132
#define WS_STRIDE 136
#define XS_FLOATS (128 * XS_STRIDE)
#define WS_FLOATS (128 * WS_STRIDE)
#define GEMM_SMEM ((XS_FLOATS + 2 * WS_FLOATS) * 4)

__global__ __launch_bounds__(256) void rgcn_gemm_mma(const float* __restrict__ x)
{
    extern __shared__ float sm[];
    float* xs = sm;
    float* ws = sm + XS_FLOATS;
    const uint32_t ws_u = smem_to_u32(ws);

    const int tid  = threadIdx.x;
    const int tile = blockIdx.x;
    const int row0 = tile * TILE_M;

    // async load W[0] / W[1] into double buffer
    for (int i = tid; i < 4096; i += 256) {
        int k = i >> 5, c = i & 31;
        cp_async16(ws_u + (uint32_t)(k * WS_STRIDE + c * 4) * 4,
                   g_wr + (size_t)k * FEAT + c * 4, 16);
    }
    CP_COMMIT();
    for (int i = tid; i < 4096; i += 256) {
        int k = i >> 5, c = i & 31;
        cp_async16(ws_u + (uint32_t)(WS_FLOATS + k * WS_STRIDE + c * 4) * 4,
                   g_wr + (size_t)FEAT * FEAT + (size_t)k * FEAT + c * 4, 16);
    }
    CP_COMMIT();

    // direct x tile load + tf32 rounding (zero-fill OOB rows)
    for (int i = tid; i < 4096; i += 256) {
        int row = i >> 5, c = i & 31;
        float4 v = make_float4(0.f, 0.f, 0.f, 0.f);
        if (row0 + row < N_NODES) v = ((const float4*)x)[(size_t)(row0 + row) * 32 + c];
        v.x = to_tf32(v.x); v.y = to_tf32(v.y); v.z = to_tf32(v.z); v.w = to_tf32(v.w);
        float* d = xs + row * XS_STRIDE + c * 4;
        d[0] = v.x; d[1] = v.y; d[2] = v.z; d[3] = v.w;
    }

    asm volatile("cp.async.wait_group 1;" ::: "memory");
    __syncthreads();

    const int wid = tid >> 5, lane = tid & 31;
    const int wm = wid >> 1, wn = wid & 1;
    const int r0 = wm * 32;
    const int n0 = wn * 64;
    const int tr = lane >> 2, tc = lane & 3;

    for (int rel = 0; rel < NUM_RELS; rel++) {
        const float* wb = ws + (rel & 1) * WS_FLOATS;

        float c[2][8][4];
        #pragma unroll
        for (int mi = 0; mi < 2; mi++)
            #pragma unroll
            for (int ni = 0; ni < 8; ni++)
                #pragma unroll
                for (int j = 0; j < 4; j++) c[mi][ni][j] = 0.f;

        #pragma unroll
        for (int kk = 0; kk < 16; kk++) {
            const int k0 = kk * 8;
            uint32_t a[2][4], b[8][2];
            #pragma unroll
            for (int mi = 0; mi < 2; mi++) {
                const int rr = r0 + mi * 16 + tr;
                a[mi][0] = __float_as_uint(xs[rr * XS_STRIDE + k0 + tc]);
                a[mi][1] = __float_as_uint(xs[(rr + 8) * XS_STRIDE + k0 + tc]);
                a[mi][2] = __float_as_uint(xs[rr * XS_STRIDE + k0 + tc + 4]);
                a[mi][3] = __float_as_uint(xs[(rr + 8) * XS_STRIDE + k0 + tc + 4]);
            }
            #pragma unroll
            for (int ni = 0; ni < 8; ni++) {
                const int nn = n0 + ni * 8 + tr;
                b[ni][0] = __float_as_uint(wb[(k0 + tc) * WS_STRIDE + nn]);
                b[ni][1] = __float_as_uint(wb[(k0 + tc + 4) * WS_STRIDE + nn]);
            }
            #pragma unroll
            for (int mi = 0; mi < 2; mi++)
                #pragma unroll
                for (int ni = 0; ni < 8; ni++)
                    mma_tf32(c[mi][ni], a[mi][0], a[mi][1], a[mi][2], a[mi][3],
                             b[ni][0], b[ni][1]);
        }

        __syncthreads();

        if (rel + 2 < NUM_RELS) {
            for (int i = tid; i < 4096; i += 256) {
                int k = i >> 5, cc = i & 31;
                cp_async16(ws_u + (uint32_t)((rel & 1) * WS_FLOATS + k * WS_STRIDE + cc * 4) * 4,
                           g_wr + (size_t)(rel + 2) * FEAT * FEAT + (size_t)k * FEAT + cc * 4, 16);
            }
            CP_COMMIT();
        }

        #pragma unroll
        for (int mi = 0; mi < 2; mi++) {
            #pragma unroll
            for (int p = 0; p < 2; p++) {
                const int row = row0 + r0 + mi * 16 + tr + p * 8;
                if (row < N_NODES) {
                    uint32_t h[8];
                    #pragma unroll
                    for (int ni = 0; ni < 8; ni++) {
                        __half2 hh = __floats2half2_rn(c[mi][ni][2 * p], c[mi][ni][2 * p + 1]);
                        h[ni] = *(uint32_t*)&hh;
                    }
                    uint4* dst = (uint4*)(g_hw_h + ((size_t)rel * N_NODES + row) * FEAT + n0 + tc * 16);
                    dst[0] = make_uint4(h[0], h[1], h[2], h[3]);
                    dst[1] = make_uint4(h[4], h[5], h[6], h[7]);
                }
            }
        }

        if (rel + 1 < NUM_RELS) {
            if (rel + 2 < NUM_RELS) { asm volatile("cp.async.wait_group 1;" ::: "memory"); }
            else                    { asm volatile("cp.async.wait_group 0;" ::: "memory"); }
            __syncthreads();
        }
    }
}

// ---------------------------------------------------------------------------
// CSR build
// ---------------------------------------------------------------------------
__global__ __launch_bounds__(256) void csr_zero_kernel()
{
    int i = blockIdx.x * blockDim.x + threadIdx.x;
    if (i < N_NODES) { g_deg[i] = 0; g_cur[i] = 0; }
}

__global__ __launch_bounds__(256) void csr_hist_kernel(const int* __restrict__ dst)
{
    int e = blockIdx.x * blockDim.x + threadIdx.x;
    if (e < N_EDGES) atomicAdd(&g_deg[dst[e]], 1);
}

__global__ __launch_bounds__(SCAN_B) void csr_scan_block_kernel()
{
    __shared__ int sh[SCAN_B];
    int i = blockIdx.x * SCAN_B + threadIdx.x;
    int v = (i < N_NODES) ? g_deg[i] : 0;
    sh[threadIdx.x] = v;
    __syncthreads();
    #pragma unroll
    for (int o = 1; o < SCAN_B; o <<= 1) {
        int t = (threadIdx.x >= o) ? sh[threadIdx.x - o] : 0;
        __syncthreads();
        sh[threadIdx.x] += t;
        __syncthreads();
    }
    if (i < N_NODES) g_rowstart[i] = sh[threadIdx.x] - v;
    if (threadIdx.x == SCAN_B - 1) g_bsum[blockIdx.x] = sh[SCAN_B - 1];
}

__global__ __launch_bounds__(SCAN_B) void csr_scan_sums_kernel()
{
    __shared__ int sh[SCAN_B];
    int v = (threadIdx.x < N_SBLK) ? g_bsum[threadIdx.x] : 0;
    sh[threadIdx.x] = v;
    __syncthreads();
    #pragma unroll
    for (int o = 1; o < SCAN_B; o <<= 1) {
        int t = (threadIdx.x >= o) ? sh[threadIdx.x - o] : 0;
        __syncthreads();
        sh[threadIdx.x] += t;
        __syncthreads();
    }
    if (threadIdx.x < N_SBLK) g_bsum[threadIdx.x] = sh[threadIdx.x] - v;
}

__global__ __launch_bounds__(256) void csr_add_offsets_kernel()
{
    int i = blockIdx.x * blockDim.x + threadIdx.x;
    if (i < N_NODES) g_rowstart[i] += g_bsum[i >> 8];
    if (i == 0) g_rowstart[N_NODES] = N_EDGES;
}

// Permute + pack: CSR-ordered (row byte offset, norm) pairs
__global__ __launch_bounds__(256) void csr_permute_kernel(
    const int* __restrict__ src, const int* __restrict__ dst,
    const int* __restrict__ rel, const float* __restrict__ norm)
{
    int e = blockIdx.x * blockDim.x + threadIdx.x;
    if (e >= N_EDGES) return;
    int d = dst[e];
    int pos = atomicAdd(&g_cur[d], 1);
    int p = g_rowstart[d] + pos;
    g_eoff[p]  = (uint32_t)((rel[e] * N_NODES + src[e]) * (FEAT * 2));
    g_enorm[p] = norm[e];
}

// ---------------------------------------------------------------------------
// Aggregate: warp per node, coalesced metadata, depth-4 pipelined row gather,
// fused bias+relu store.
// ---------------------------------------------------------------------------
__global__ __launch_bounds__(256) void rgcn_aggregate_kernel(
    const float* __restrict__ bias, float* __restrict__ out)
{
    const int warp = (blockIdx.x * blockDim.x + threadIdx.x) >> 5;
    const int lane = threadIdx.x & 31;
    if (warp >= N_NODES) return;

    const int beg = g_rowstart[warp];
    const int end = g_rowstart[warp + 1];

    const char* hwb = (const char*)g_hw_h;
    float4 acc = make_float4(0.f, 0.f, 0.f, 0.f);

    for (int base = beg; base < end; base += 32) {
        int m = end - base; if (m > 32) m = 32;
        uint32_t off_l = 0; float nm_l = 0.f;
        if (lane < m) { off_l = g_eoff[base + lane]; nm_l = g_enorm[base + lane]; }

        uint2 pre[4];
        #pragma unroll
        for (int j = 0; j < 4; j++) {
            if (j < m) {
                uint32_t o = __shfl_sync(0xffffffffu, off_l, j);
                pre[j] = ((const uint2*)(hwb + o))[lane];
            }
        }

        for (int i = 0; i < m; i++) {
            const float nm  = __shfl_sync(0xffffffffu, nm_l, i);
            const uint2 cur = pre[i & 3];
            if (i + 4 < m) {
                uint32_t o = __shfl_sync(0xffffffffu, off_l, i + 4);
                pre[i & 3] = ((const uint2*)(hwb + o))[lane];
            }
            float2 f0 = __half22float2(*(const __half2*)&cur.x);
            float2 f1 = __half22float2(*(const __half2*)&cur.y);
            acc.x = fmaf(f0.x, nm, acc.x);
            acc.y = fmaf(f0.y, nm, acc.y);
            acc.z = fmaf(f1.x, nm, acc.z);
            acc.w = fmaf(f1.y, nm, acc.w);
        }
    }

    const float4 b = ((const float4*)bias)[lane];
    acc.x = fmaxf(acc.x + b.x, 0.f);
    acc.y = fmaxf(acc.y + b.y, 0.f);
    acc.z = fmaxf(acc.z + b.z, 0.f);
    acc.w = fmaxf(acc.w + b.w, 0.f);
    ((float4*)(out + (size_t)warp * FEAT))[lane] = acc;
}

// ---------------------------------------------------------------------------
extern "C" void kernel_launch(void* const* d_in, const int* in_sizes, int n_in,
                              void* d_out, int out_size)
{
    const float* x      = (const float*)d_in[0];
    const float* norm   = (const float*)d_in[1];
    const float* weight = (const float*)d_in[2];
    const float* bias   = (const float*)d_in[3];
    const int*   src    = (const int*)d_in[4];
    const int*   dst    = (const int*)d_in[5];
    const int*   rel    = (const int*)d_in[6];
    float*       out    = (float*)d_out;

    cudaFuncSetAttribute(rgcn_gemm_mma, cudaFuncAttributeMaxDynamicSharedMemorySize, GEMM_SMEM);

    // CSR build
    csr_zero_kernel<<<(N_NODES + 255) / 256, 256>>>();
    csr_hist_kernel<<<(N_EDGES + 255) / 256, 256>>>(dst);
    csr_scan_block_kernel<<<N_SBLK, SCAN_B>>>();
    csr_scan_sums_kernel<<<1, SCAN_B>>>();
    csr_add_offsets_kernel<<<(N_NODES + 255) / 256, 256>>>();
    csr_permute_kernel<<<(N_EDGES + 255) / 256, 256>>>(src, dst, rel, norm);

    // transform
    prep_w_kernel<<<(NUM_RELS * FEAT * FEAT + 255) / 256, 256>>>(weight);
    rgcn_gemm_mma<<<N_TILES, 256, GEMM_SMEM>>>(x);

    // aggregate + fused bias/relu
    const int ablocks = (N_NODES * 32 + 255) / 256;
    rgcn_aggregate_kernel<<<ablocks, 256>>>(bias, out);
}

// round 6
// speedup vs baseline: 2.4373x; 1.0966x over previous
#include <cuda_runtime.h>
#include <cuda_fp16.h>
#include <cstdint>

#define N_NODES 50000
#define N_EDGES 1600000
#define FEAT    128
#define NUM_RELS 8
#define TILE_M  128
#define N_TILES 391              /* ceil(50000/128) */
#define SCAN_B  256
#define N_SBLK  ((N_NODES + SCAN_B - 1) / SCAN_B)   /* 196 */

// ---------------------------------------------------------------------------
// Device scratch
// ---------------------------------------------------------------------------
__device__ __half    g_hw_h[(size_t)NUM_RELS * N_NODES * FEAT]; // 102.4 MB fp16
__device__ __half    g_wr_h[(size_t)NUM_RELS * FEAT * FEAT];    // 256 KB fp16, [r][s][k] (k-contig)
__device__ int       g_deg[N_NODES];
__device__ int       g_cur[N_NODES];
__device__ int       g_rowstart[N_NODES + 1];
__device__ int       g_bsum[N_SBLK];
__device__ uint2     g_emeta[N_EDGES];                          // {hw-row byte offset, norm bits}

// ---------------------------------------------------------------------------
// Helpers
// ---------------------------------------------------------------------------
__device__ __forceinline__ uint32_t smem_to_u32(const void* p) {
    uint32_t a;
    asm("{ .reg .u64 t; cvta.to.shared.u64 t, %1; cvt.u32.u64 %0, t; }" : "=r"(a) : "l"(p));
    return a;
}
__device__ __forceinline__ void cp_async16(uint32_t dst, const void* src) {
    asm volatile("cp.async.cg.shared.global [%0], [%1], 16;"
                 :: "r"(dst), "l"(src) : "memory");
}
#define CP_COMMIT() asm volatile("cp.async.commit_group;" ::: "memory")

__device__ __forceinline__ void mma_f16(float c[4],
                                        uint32_t a0, uint32_t a1, uint32_t a2, uint32_t a3,
                                        uint32_t b0, uint32_t b1) {
    asm volatile("mma.sync.aligned.m16n8k16.row.col.f32.f16.f16.f32 "
                 "{%0,%1,%2,%3}, {%4,%5,%6,%7}, {%8,%9}, {%0,%1,%2,%3};"
                 : "+f"(c[0]), "+f"(c[1]), "+f"(c[2]), "+f"(c[3])
                 : "r"(a0), "r"(a1), "r"(a2), "r"(a3), "r"(b0), "r"(b1));
}

// ---------------------------------------------------------------------------
// Prep: W[r][k][o] -> fp16, column-permuted + transposed to [r][s][k]
// (k contiguous so the mma B fragment is a single half2 load).
// Permutation: smem col position s maps to global out col
//   g(s) = (s/64)*64 + ((s%8)/2)*16 + ((s%64)/8)*2 + (s&1)
// ---------------------------------------------------------------------------
__global__ __launch_bounds__(256) void prep_w_kernel(const float* __restrict__ w)
{
    int i = blockIdx.x * blockDim.x + threadIdx.x;
    if (i >= NUM_RELS * FEAT * FEAT) return;
    int r = i >> 14, j = i & 16383;
    int s = j >> 7, k = j & 127;
    int g = (s >> 6) * 64 + ((s & 7) >> 1) * 16 + ((s & 63) >> 3) * 2 + (s & 1);
    g_wr_h[i] = __float2half_rn(w[((size_t)r * FEAT + k) * FEAT + g]);
}

// ---------------------------------------------------------------------------
// GEMM via mma.sync fp16 (m16n8k16). x loaded direct, converted fp16 in smem.
// smem (halfs): xs [128][136], W dbuf 2x[128][136]  -> 104448 bytes total.
// ---------------------------------------------------------------------------
#define XS_STRIDE 136
#define WS_STRIDE 136
#define XS_HALFS (128 * XS_STRIDE)
#define WS_HALFS (128 * WS_STRIDE)
#define GEMM_SMEM ((XS_HALFS + 2 * WS_HALFS) * 2)

__global__ __launch_bounds__(256) void rgcn_gemm_mma(const float* __restrict__ x)
{
    extern __shared__ __half sm[];
    __half* xs = sm;
    __half* ws = sm + XS_HALFS;
    const uint32_t ws_u = smem_to_u32(ws);

    const int tid  = threadIdx.x;
    const int tile = blockIdx.x;
    const int row0 = tile * TILE_M;

    // async load W[0] / W[1] (32 KB each: 2048 x 16B)
    for (int i = tid; i < 2048; i += 256) {
        int s = i >> 4, c = i & 15;
        cp_async16(ws_u + (uint32_t)(s * WS_STRIDE + c * 8) * 2,
                   g_wr_h + (size_t)s * FEAT + c * 8);
    }
    CP_COMMIT();
    for (int i = tid; i < 2048; i += 256) {
        int s = i >> 4, c = i & 15;
        cp_async16(ws_u + (uint32_t)(WS_HALFS + s * WS_STRIDE + c * 8) * 2,
                   g_wr_h + (size_t)FEAT * FEAT + (size_t)s * FEAT + c * 8);
    }
    CP_COMMIT();

    // direct x tile load + fp16 convert (zero-fill OOB rows)
    for (int i = tid; i < 4096; i += 256) {
        int row = i >> 5, c = i & 31;
        float4 v = make_float4(0.f, 0.f, 0.f, 0.f);
        if (row0 + row < N_NODES) v = ((const float4*)x)[(size_t)(row0 + row) * 32 + c];
        __half2 h0 = __floats2half2_rn(v.x, v.y);
        __half2 h1 = __floats2half2_rn(v.z, v.w);
        uint2* d = (uint2*)&xs[row * XS_STRIDE + c * 4];
        *d = make_uint2(*(uint32_t*)&h0, *(uint32_t*)&h1);
    }

    asm volatile("cp.async.wait_group 1;" ::: "memory");
    __syncthreads();

    const int wid = tid >> 5, lane = tid & 31;
    const int wm = wid >> 1, wn = wid & 1;
    const int r0 = wm * 32;
    const int n0 = wn * 64;
    const int tr = lane >> 2;
    const int tc2 = (lane & 3) * 2;
    const int tc = lane & 3;

    for (int rel = 0; rel < NUM_RELS; rel++) {
        const __half* wb = ws + (rel & 1) * WS_HALFS;

        float c[2][8][4];
        #pragma unroll
        for (int mi = 0; mi < 2; mi++)
            #pragma unroll
            for (int ni = 0; ni < 8; ni++)
                #pragma unroll
                for (int j = 0; j < 4; j++) c[mi][ni][j] = 0.f;

        #pragma unroll
        for (int kk = 0; kk < 8; kk++) {
            const int k0 = kk * 16;
            uint32_t a[2][4], b[8][2];
            #pragma unroll
            for (int mi = 0; mi < 2; mi++) {
                const int rr = r0 + mi * 16 + tr;
                a[mi][0] = *(const uint32_t*)&xs[rr * XS_STRIDE + k0 + tc2];
                a[mi][1] = *(const uint32_t*)&xs[(rr + 8) * XS_STRIDE + k0 + tc2];
                a[mi][2] = *(const uint32_t*)&xs[rr * XS_STRIDE + k0 + tc2 + 8];
                a[mi][3] = *(const uint32_t*)&xs[(rr + 8) * XS_STRIDE + k0 + tc2 + 8];
            }
            #pragma unroll
            for (int ni = 0; ni < 8; ni++) {
                const int nn = n0 + ni * 8 + tr;
                b[ni][0] = *(const uint32_t*)&wb[nn * WS_STRIDE + k0 + tc2];
                b[ni][1] = *(const uint32_t*)&wb[nn * WS_STRIDE + k0 + tc2 + 8];
            }
            #pragma unroll
            for (int mi = 0; mi < 2; mi++)
                #pragma unroll
                for (int ni = 0; ni < 8; ni++)
                    mma_f16(c[mi][ni], a[mi][0], a[mi][1], a[mi][2], a[mi][3],
                            b[ni][0], b[ni][1]);
        }

        __syncthreads();

        if (rel + 2 < NUM_RELS) {
            for (int i = tid; i < 2048; i += 256) {
                int s = i >> 4, cc = i & 15;
                cp_async16(ws_u + (uint32_t)((rel & 1) * WS_HALFS + s * WS_STRIDE + cc * 8) * 2,
                           g_wr_h + (size_t)(rel + 2) * FEAT * FEAT + (size_t)s * FEAT + cc * 8);
            }
            CP_COMMIT();
        }

        // Epilogue: thread owns global cols [n0 + tc*16, +16) (same C layout as k8)
        #pragma unroll
        for (int mi = 0; mi < 2; mi++) {
            #pragma unroll
            for (int p = 0; p < 2; p++) {
                const int row = row0 + r0 + mi * 16 + tr + p * 8;
                if (row < N_NODES) {
                    uint32_t h[8];
                    #pragma unroll
                    for (int ni = 0; ni < 8; ni++) {
                        __half2 hh = __floats2half2_rn(c[mi][ni][2 * p], c[mi][ni][2 * p + 1]);
                        h[ni] = *(uint32_t*)&hh;
                    }
                    uint4* dst = (uint4*)(g_hw_h + ((size_t)rel * N_NODES + row) * FEAT + n0 + tc * 16);
                    dst[0] = make_uint4(h[0], h[1], h[2], h[3]);
                    dst[1] = make_uint4(h[4], h[5], h[6], h[7]);
                }
            }
        }

        if (rel + 1 < NUM_RELS) {
            if (rel + 2 < NUM_RELS) { asm volatile("cp.async.wait_group 1;" ::: "memory"); }
            else                    { asm volatile("cp.async.wait_group 0;" ::: "memory"); }
            __syncthreads();
        }
    }
}

// ---------------------------------------------------------------------------
// CSR build
// ---------------------------------------------------------------------------
__global__ __launch_bounds__(256) void csr_zero_kernel()
{
    int i = blockIdx.x * blockDim.x + threadIdx.x;
    if (i < N_NODES) { g_deg[i] = 0; g_cur[i] = 0; }
}

__global__ __launch_bounds__(256) void csr_hist_kernel(const int* __restrict__ dst)
{
    int e = blockIdx.x * blockDim.x + threadIdx.x;
    if (e < N_EDGES) atomicAdd(&g_deg[dst[e]], 1);
}

__global__ __launch_bounds__(SCAN_B) void csr_scan_block_kernel()
{
    __shared__ int sh[SCAN_B];
    int i = blockIdx.x * SCAN_B + threadIdx.x;
    int v = (i < N_NODES) ? g_deg[i] : 0;
    sh[threadIdx.x] = v;
    __syncthreads();
    #pragma unroll
    for (int o = 1; o < SCAN_B; o <<= 1) {
        int t = (threadIdx.x >= o) ? sh[threadIdx.x - o] : 0;
        __syncthreads();
        sh[threadIdx.x] += t;
        __syncthreads();
    }
    if (i < N_NODES) g_rowstart[i] = sh[threadIdx.x] - v;
    if (threadIdx.x == SCAN_B - 1) g_bsum[blockIdx.x] = sh[SCAN_B - 1];
}

__global__ __launch_bounds__(SCAN_B) void csr_scan_sums_kernel()
{
    __shared__ int sh[SCAN_B];
    int v = (threadIdx.x < N_SBLK) ? g_bsum[threadIdx.x] : 0;
    sh[threadIdx.x] = v;
    __syncthreads();
    #pragma unroll
    for (int o = 1; o < SCAN_B; o <<= 1) {
        int t = (threadIdx.x >= o) ? sh[threadIdx.x - o] : 0;
        __syncthreads();
        sh[threadIdx.x] += t;
        __syncthreads();
    }
    if (threadIdx.x < N_SBLK) g_bsum[threadIdx.x] = sh[threadIdx.x] - v;
}

__global__ __launch_bounds__(256) void csr_add_offsets_kernel()
{
    int i = blockIdx.x * blockDim.x + threadIdx.x;
    if (i < N_NODES) g_rowstart[i] += g_bsum[i >> 8];
    if (i == 0) g_rowstart[N_NODES] = N_EDGES;
}

// Permute + pack: CSR-ordered {hw-row byte offset, norm} pairs
__global__ __launch_bounds__(256) void csr_permute_kernel(
    const int* __restrict__ src, const int* __restrict__ dst,
    const int* __restrict__ rel, const float* __restrict__ norm)
{
    int e = blockIdx.x * blockDim.x + threadIdx.x;
    if (e >= N_EDGES) return;
    int d = dst[e];
    int pos = atomicAdd(&g_cur[d], 1);
    int p = g_rowstart[d] + pos;
    uint32_t off = (uint32_t)((rel[e] * N_NODES + src[e]) * (FEAT * 2));
    g_emeta[p] = make_uint2(off, __float_as_uint(norm[e]));
}

// ---------------------------------------------------------------------------
// Aggregate: warp per node, one LDG.64 metadata/lane/chunk, depth-8 pipelined
// row gather (full-chunk path fully unrolled -> ring stays in registers),
// fused bias+relu store.
// ---------------------------------------------------------------------------
__global__ __launch_bounds__(256) void rgcn_aggregate_kernel(
    const float* __restrict__ bias, float* __restrict__ out)
{
    const int warp = (blockIdx.x * blockDim.x + threadIdx.x) >> 5;
    const int lane = threadIdx.x & 31;
    if (warp >= N_NODES) return;

    const int beg = g_rowstart[warp];
    const int end = g_rowstart[warp + 1];

    const char* hwb = (const char*)g_hw_h;
    float4 acc = make_float4(0.f, 0.f, 0.f, 0.f);

    for (int base = beg; base < end; base += 32) {
        const int m = min(32, end - base);
        uint2 mt = make_uint2(0u, 0u);
        if (lane < m) mt = g_emeta[base + lane];

        if (m == 32) {
            uint2 pre[8];
            #pragma unroll
            for (int j = 0; j < 8; j++) {
                uint32_t o = __shfl_sync(0xffffffffu, mt.x, j);
                pre[j] = ((const uint2*)(hwb + o))[lane];
            }
            #pragma unroll
            for (int i = 0; i < 32; i++) {
                const float nm  = __uint_as_float(__shfl_sync(0xffffffffu, mt.y, i));
                const uint2 cur = pre[i & 7];
                if (i + 8 < 32) {
                    uint32_t o = __shfl_sync(0xffffffffu, mt.x, i + 8);
                    pre[i & 7] = ((const uint2*)(hwb + o))[lane];
                }
                float2 f0 = __half22float2(*(const __half2*)&cur.x);
                float2 f1 = __half22float2(*(const __half2*)&cur.y);
                acc.x = fmaf(f0.x, nm, acc.x);
                acc.y = fmaf(f0.y, nm, acc.y);
                acc.z = fmaf(f1.x, nm, acc.z);
                acc.w = fmaf(f1.y, nm, acc.w);
            }
        } else {
            #pragma unroll 4
            for (int i = 0; i < m; i++) {
                const float nm = __uint_as_float(__shfl_sync(0xffffffffu, mt.y, i));
                uint32_t o = __shfl_sync(0xffffffffu, mt.x, i);
                uint2 cur = ((const uint2*)(hwb + o))[lane];
                float2 f0 = __half22float2(*(const __half2*)&cur.x);
                float2 f1 = __half22float2(*(const __half2*)&cur.y);
                acc.x = fmaf(f0.x, nm, acc.x);
                acc.y = fmaf(f0.y, nm, acc.y);
                acc.z = fmaf(f1.x, nm, acc.z);
                acc.w = fmaf(f1.y, nm, acc.w);
            }
        }
    }

    const float4 b = ((const float4*)bias)[lane];
    acc.x = fmaxf(acc.x + b.x, 0.f);
    acc.y = fmaxf(acc.y + b.y, 0.f);
    acc.z = fmaxf(acc.z + b.z, 0.f);
    acc.w = fmaxf(acc.w + b.w, 0.f);
    ((float4*)(out + (size_t)warp * FEAT))[lane] = acc;
}

// ---------------------------------------------------------------------------
extern "C" void kernel_launch(void* const* d_in, const int* in_sizes, int n_in,
                              void* d_out, int out_size)
{
    const float* x      = (const float*)d_in[0];
    const float* norm   = (const float*)d_in[1];
    const float* weight = (const float*)d_in[2];
    const float* bias   = (const float*)d_in[3];
    const int*   src    = (const int*)d_in[4];
    const int*   dst    = (const int*)d_in[5];
    const int*   rel    = (const int*)d_in[6];
    float*       out    = (float*)d_out;

    cudaFuncSetAttribute(rgcn_gemm_mma, cudaFuncAttributeMaxDynamicSharedMemorySize, GEMM_SMEM);

    // CSR build
    csr_zero_kernel<<<(N_NODES + 255) / 256, 256>>>();
    csr_hist_kernel<<<(N_EDGES + 255) / 256, 256>>>(dst);
    csr_scan_block_kernel<<<N_SBLK, SCAN_B>>>();
    csr_scan_sums_kernel<<<1, SCAN_B>>>();
    csr_add_offsets_kernel<<<(N_NODES + 255) / 256, 256>>>();
    csr_permute_kernel<<<(N_EDGES + 255) / 256, 256>>>(src, dst, rel, norm);

    // transform
    prep_w_kernel<<<(NUM_RELS * FEAT * FEAT + 255) / 256, 256>>>(weight);
    rgcn_gemm_mma<<<N_TILES, 256, GEMM_SMEM>>>(x);

    // aggregate + fused bias/relu
    const int ablocks = (N_NODES * 32 + 255) / 256;
    rgcn_aggregate_kernel<<<ablocks, 256>>>(bias, out);
}